// round 10
// baseline (speedup 1.0000x reference)
#include <cuda_runtime.h>
#include <cstdint>

#define NB 8192
#define NP 8192
#define NF 256
#define BM 128
#define BN 128
#define STAGES 3
#define AKB 16384           // 128x32 fp32 block bytes (A or B)
#define STAGE_B (2 * AKB)   // 32 KB
#define SMEM_BYTES (STAGES * STAGE_B)  // 96 KB
#define GKT 16              // 2 tiles x 8 k-steps, one fused stream

// ---------------- device scratch (allocation-free) ----------------
__device__ float g_xsq[NB];
__device__ float g_psq[NP];
// fragment-order permuted tf32 copies: [tile(64)][kb(8)][16KB block]
__device__ __align__(1024) float g_Xr[(size_t)NB * NF];
__device__ __align__(1024) float g_Pr[(size_t)NP * NF];

__device__ __forceinline__ uint32_t smem_u32(const void* p) {
    uint32_t a;
    asm("{ .reg .u64 t; cvta.to.shared.u64 t, %1; cvt.u32.u64 %0, t; }" : "=r"(a) : "l"(p));
    return a;
}

// ---------------- prepass: tf32 round + permute + row norms ----------------
// warp per row; lane g handles k = g*8 .. g*8+7  (kb = g>>2, ak = g&3, cc = 0..7)
// A block: atom = 16 m x 8 k = 512B, idx = ak*8 + am
//   off = idx*512 + ((rr&7)*4 + (cc&3))*16 + ((rr>>3)|((cc>>2)<<1))*4
// B block: atom = 16 n x 8 k = 512B (two n8 subtiles), idx = ak*8 + pn
//   off = idx*512 + (nn*4 + (cc&3))*16 + sub*8 + (cc>>2)*4
__global__ __launch_bounds__(256) void prep_kernel(const float* __restrict__ X,
                                                   const float* __restrict__ P) {
    const bool isP = blockIdx.x >= (NB / 8);
    const int rbase = (isP ? blockIdx.x - NB / 8 : blockIdx.x) * 8;
    const int g = threadIdx.x & 31;
    const int r = rbase + (threadIdx.x >> 5);

    const float* src = (isP ? P : X) + (size_t)r * NF + g * 8;
    float4 v0 = *reinterpret_cast<const float4*>(src);
    float4 v1 = *reinterpret_cast<const float4*>(src + 4);
    float vv[8] = {v0.x, v0.y, v0.z, v0.w, v1.x, v1.y, v1.z, v1.w};

    float s = 0.f;
    #pragma unroll
    for (int i = 0; i < 8; i++) s += vv[i] * vv[i];
    #pragma unroll
    for (int o = 16; o > 0; o >>= 1) s += __shfl_xor_sync(0xffffffffu, s, o);
    if (g == 0) (isP ? g_psq : g_xsq)[r] = s;

    const int kb = g >> 2, ak = g & 3;
    char* base;
    uint32_t abase;
    int rin;
    if (!isP) {
        rin = r & 127;
        base = (char*)g_Xr + (((size_t)(r >> 7) * 8 + kb) << 14);
    } else {
        rin = r & 127;
        base = (char*)g_Pr + (((size_t)(r >> 7) * 8 + kb) << 14);
    }
    #pragma unroll
    for (int cc = 0; cc < 8; cc++) {
        uint32_t u;
        asm("cvt.rna.tf32.f32 %0, %1;" : "=r"(u) : "f"(vv[cc]));
        uint32_t off;
        if (!isP) {
            int am = rin >> 4, rr = rin & 15;
            off = ((uint32_t)(ak * 8 + am) << 9)
                + (uint32_t)((rr & 7) * 4 + (cc & 3)) * 16u
                + ((uint32_t)((rr >> 3) | ((cc >> 2) << 1)) << 2);
        } else {
            int pn = rin >> 4, sub = (rin >> 3) & 1, nn = rin & 7;
            off = ((uint32_t)(ak * 8 + pn) << 9)
                + (uint32_t)(nn * 4 + (cc & 3)) * 16u
                + (uint32_t)(sub * 8)
                + ((uint32_t)(cc >> 2) << 2);
        }
        *reinterpret_cast<float*>(base + off) = __uint_as_float(u);
    }
}

// ---------------- main kernel: 2 fused 128x128 tiles per CTA ----------------
__global__ __launch_bounds__(256, 2) void gauss_mma_kernel(float* __restrict__ out) {
    extern __shared__ char sm[];
    const uint32_t sb = smem_u32(sm);

    // pair mapping: ids 2c, 2c+1 share tm (same A stream), tn1 = tn0 + 1
    const int id0 = blockIdx.x * 2;
    const int tn0 = ((id0 >> 10) << 4) | (id0 & 15);
    const int tm  = (id0 & 1023) >> 4;
    const int tn1 = tn0 + 1;

    const int tid = threadIdx.x;
    const int w = tid >> 5, lane = tid & 31;
    const int wm = w & 1, wn = w >> 1;      // 2(M) x 4(N); warp tile 64x32
    const int g = lane >> 2, tg = lane & 3;
    const int phw = (w & 1) << 1;           // per-warp sub-k phase (0 or 2)

    const char* gA  = (const char*)g_Xr + ((size_t)tm  * 8 << 14);
    const char* gB0 = (const char*)g_Pr + ((size_t)tn0 * 8 << 14);
    const char* gB1 = (const char*)g_Pr + ((size_t)tn1 * 8 << 14);

    auto issue = [&](int gk) {   // gk compile-time under full unroll
        const char* a = gA + ((size_t)(gk & 7) << 14) + tid * 64;
        const char* b = ((gk < 8) ? gB0 : gB1) + ((size_t)(gk & 7) << 14) + tid * 64;
        const uint32_t so = sb + (uint32_t)(gk % 3) * STAGE_B + (uint32_t)tid * 64;
        #pragma unroll
        for (int j = 0; j < 4; j++) {
            asm volatile("cp.async.cg.shared.global [%0], [%1], 16;" :: "r"(so + j * 16), "l"(a + j * 16));
            asm volatile("cp.async.cg.shared.global [%0], [%1], 16;" :: "r"(so + AKB + j * 16), "l"(b + j * 16));
        }
        asm volatile("cp.async.commit_group;" ::: "memory");
    };

    float acc[4][4][4];
    #pragma unroll
    for (int mt = 0; mt < 4; mt++)
        #pragma unroll
        for (int nt = 0; nt < 4; nt++)
            #pragma unroll
            for (int q = 0; q < 4; q++) acc[mt][nt][q] = 0.f;

    const uint32_t laneOff = (uint32_t)lane * 16;
    uint32_t af[2][4][4];   // [buf][mt][a0..a3]
    uint32_t bf[2][2][4];   // [buf][pair][b0_lo, b1_lo, b0_hi, b1_hi]

    // ac is warp-uniform (loop-ak ^ phase) — addresses stay uniform-ALU only
    auto ldfrags = [&](int buf, uint32_t so, int ac) {
        #pragma unroll
        for (int mt = 0; mt < 4; mt++) {
            uint32_t addr = so + ((uint32_t)(ac * 8 + wm * 4 + mt) << 9) + laneOff;
            asm volatile("ld.shared.v4.b32 {%0,%1,%2,%3}, [%4];"
                         : "=r"(af[buf][mt][0]), "=r"(af[buf][mt][1]),
                           "=r"(af[buf][mt][2]), "=r"(af[buf][mt][3]) : "r"(addr));
        }
        #pragma unroll
        for (int pp = 0; pp < 2; pp++) {
            uint32_t addr = so + AKB + ((uint32_t)(ac * 8 + wn * 2 + pp) << 9) + laneOff;
            asm volatile("ld.shared.v4.b32 {%0,%1,%2,%3}, [%4];"
                         : "=r"(bf[buf][pp][0]), "=r"(bf[buf][pp][1]),
                           "=r"(bf[buf][pp][2]), "=r"(bf[buf][pp][3]) : "r"(addr));
        }
    };

    auto epilogue = [&](int tn) {
        const int orow0 = tm * BM + wm * 64 + g;
        const int ocol0 = tn * BN + wn * 32 + 2 * tg;
        #pragma unroll
        for (int mt = 0; mt < 4; mt++) {
            const int r0 = orow0 + mt * 16;
            const float xs0 = g_xsq[r0];
            const float xs1 = g_xsq[r0 + 8];
            float* orow_a = out + (size_t)r0 * NP;
            float* orow_b = out + (size_t)(r0 + 8) * NP;
            #pragma unroll
            for (int nt = 0; nt < 4; nt++) {
                const int cc = ocol0 + nt * 8;
                const float p0 = g_psq[cc];
                const float p1 = g_psq[cc + 1];
                float d00 = fmaxf(fmaf(-2.f, acc[mt][nt][0], xs0 + p0), 1e-30f);
                float d01 = fmaxf(fmaf(-2.f, acc[mt][nt][1], xs0 + p1), 1e-30f);
                float d10 = fmaxf(fmaf(-2.f, acc[mt][nt][2], xs1 + p0), 1e-30f);
                float d11 = fmaxf(fmaf(-2.f, acc[mt][nt][3], xs1 + p1), 1e-30f);
                float2 v0 = make_float2(__expf(-0.5f * d00 * rsqrtf(d00)),
                                        __expf(-0.5f * d01 * rsqrtf(d01)));
                float2 v1 = make_float2(__expf(-0.5f * d10 * rsqrtf(d10)),
                                        __expf(-0.5f * d11 * rsqrtf(d11)));
                *reinterpret_cast<float2*>(orow_a + cc) = v0;
                *reinterpret_cast<float2*>(orow_b + cc) = v1;
            }
        }
    };

    // prologue
    issue(0);
    issue(1);
    asm volatile("cp.async.wait_group 1;" ::: "memory");
    __syncthreads();
    ldfrags(0, sb, phw);

    #pragma unroll
    for (int gkt = 0; gkt < GKT; gkt++) {
        const uint32_t so = sb + (uint32_t)(gkt % 3) * STAGE_B;
        #pragma unroll
        for (int ak = 0; ak < 4; ak++) {
            if (ak == 0) {
                if (gkt + 2 < GKT) issue(gkt + 2);
            }
            if (ak < 3) {
                ldfrags((ak + 1) & 1, so, (ak + 1) ^ phw);
            } else if (gkt + 1 < GKT) {
                // stage boundary before the last MMA block of this gkt
                if (gkt + 2 < GKT) {
                    asm volatile("cp.async.wait_group 1;" ::: "memory");
                } else {
                    asm volatile("cp.async.wait_group 0;" ::: "memory");
                }
                __syncthreads();
                ldfrags(0, sb + (uint32_t)((gkt + 1) % 3) * STAGE_B, phw);
            }
            const int cur = ak & 1;
            #pragma unroll
            for (int mt = 0; mt < 4; mt++)
                #pragma unroll
                for (int nt = 0; nt < 4; nt++) {
                    const int pp = nt >> 1, ss = (nt & 1) * 2;
                    asm volatile(
                        "mma.sync.aligned.m16n8k8.row.col.f32.tf32.tf32.f32 "
                        "{%0,%1,%2,%3}, {%4,%5,%6,%7}, {%8,%9}, {%0,%1,%2,%3};"
                        : "+f"(acc[mt][nt][0]), "+f"(acc[mt][nt][1]),
                          "+f"(acc[mt][nt][2]), "+f"(acc[mt][nt][3])
                        : "r"(af[cur][mt][0]), "r"(af[cur][mt][1]),
                          "r"(af[cur][mt][2]), "r"(af[cur][mt][3]),
                          "r"(bf[cur][pp][ss]), "r"(bf[cur][pp][ss + 1]));
                }
        }
        if (gkt == 7) {
            epilogue(tn0);
            #pragma unroll
            for (int mt = 0; mt < 4; mt++)
                #pragma unroll
                for (int nt = 0; nt < 4; nt++)
                    #pragma unroll
                    for (int q = 0; q < 4; q++) acc[mt][nt][q] = 0.f;
        }
    }
    epilogue(tn1);
}

// ---------------- launch ----------------
extern "C" void kernel_launch(void* const* d_in, const int* in_sizes, int n_in,
                              void* d_out, int out_size) {
    const float* x = (const float*)d_in[0];   // [8192, 256]
    const float* p = (const float*)d_in[1];   // [8192, 256]
    float* out = (float*)d_out;               // [8192, 8192]

    static bool configured = false;
    if (!configured) {
        cudaFuncSetAttribute(gauss_mma_kernel,
                             cudaFuncAttributeMaxDynamicSharedMemorySize, SMEM_BYTES);
        configured = true;
    }

    prep_kernel<<<(NB + NP) / 8, 256>>>(x, p);

    gauss_mma_kernel<<<(NB / BM) * (NP / BN) / 2, 256, SMEM_BYTES>>>(out);
}